// round 5
// baseline (speedup 1.0000x reference)
#include <cuda_runtime.h>
#include <cuda_bf16.h>
#include <math.h>
#include <stdint.h>

// Problem dims
#define TT 512
#define BB 64
#define EE 512
#define HD 512
#define HH 1024
#define CC 16
#define START_TAG 14
#define STOP_TAG 15
#define NG 4096          // 2 dirs * 4 gates * HD
#define MROWS (TT*BB)    // 32768

// ---------------- scratch (device globals; no runtime allocation) ------------
__device__ float g_X0[(size_t)MROWS * EE];                    //  64 MB
__device__ float g_G [(size_t)MROWS * NG];                    // 512 MB
__device__ float g_H0[(size_t)MROWS * HH];                    // 128 MB
__device__ float g_H1[(size_t)MROWS * HH];                    // 128 MB
__device__ __nv_bfloat16 g_As[(size_t)MROWS * 6 * HH];        // 384 MB (split A)
__device__ __nv_bfloat16 g_Ws[(size_t)NG * 6 * HH];           //  48 MB (split W)
__device__ float g_feats[(size_t)BB * TT * CC];
__device__ float g_hbuf[2 * 2 * BB * HD];

// grid barrier state
__device__ unsigned int g_bar_count;
__device__ unsigned int g_bar_gen;

__device__ __forceinline__ void grid_barrier(int nblk) {
    __syncthreads();
    if (threadIdx.x == 0) {
        __threadfence();
        unsigned int gen = *(volatile unsigned int*)&g_bar_gen;
        if (atomicAdd(&g_bar_count, 1u) == (unsigned)(nblk - 1)) {
            g_bar_count = 0;
            __threadfence();
            atomicAdd(&g_bar_gen, 1u);
        } else {
            unsigned int cur;
            do {
                asm volatile("ld.acquire.gpu.u32 %0, [%1];"
                             : "=r"(cur) : "l"(&g_bar_gen));
            } while (cur == gen);
        }
    }
    __syncthreads();
}

__device__ __forceinline__ uint32_t smem_u32(const void* p) {
    uint32_t a;
    asm("{ .reg .u64 t; cvta.to.shared.u64 t, %1; cvt.u32.u64 %0, t; }"
        : "=r"(a) : "l"(p));
    return a;
}

// ---------------- embedding gather -------------------------------------------
__global__ void embed_kernel(const int* __restrict__ sent,
                             const float* __restrict__ emb,
                             float* __restrict__ X0) {
    int m = blockIdx.x;
    int t = m >> 6;
    int b = m & 63;
    int tok = sent[b * TT + t];
    const float4* src = reinterpret_cast<const float4*>(emb + (size_t)tok * EE);
    float4* dst = reinterpret_cast<float4*>(X0 + (size_t)m * EE);
    dst[threadIdx.x] = src[threadIdx.x];
}

// ---------------- fp32 -> 3-term bf16 split (K-concatenated) -----------------
// products formed: (a0,b0) (a0,b1) (a1,b0) (a0,b2) (a1,b1) (a2,b0)
// A side: slot p uses a-term {0,0,1,0,1,2}
__global__ void splitA_kernel(const float* __restrict__ X,
                              __nv_bfloat16* __restrict__ Y,
                              int K, long long total) {
    long long idx = (long long)blockIdx.x * blockDim.x + threadIdx.x;
    if (idx >= total) return;
    int m = (int)(idx / K);
    int k = (int)(idx % K);
    float a = X[idx];
    __nv_bfloat16 b0 = __float2bfloat16(a);
    float r = a - __bfloat162float(b0);
    __nv_bfloat16 b1 = __float2bfloat16(r);
    float r2 = r - __bfloat162float(b1);
    __nv_bfloat16 b2 = __float2bfloat16(r2);
    __nv_bfloat16* base = Y + (size_t)m * 6 * K + k;
    base[0 * K] = b0; base[1 * K] = b0; base[2 * K] = b1;
    base[3 * K] = b0; base[4 * K] = b1; base[5 * K] = b2;
}
// W side: slot p uses w-term {0,1,0,2,1,0}
__global__ void splitW_kernel(const float* __restrict__ X,
                              __nv_bfloat16* __restrict__ Y,
                              int K, long long total) {
    long long idx = (long long)blockIdx.x * blockDim.x + threadIdx.x;
    if (idx >= total) return;
    int m = (int)(idx / K);
    int k = (int)(idx % K);
    float a = X[idx];
    __nv_bfloat16 b0 = __float2bfloat16(a);
    float r = a - __bfloat162float(b0);
    __nv_bfloat16 b1 = __float2bfloat16(r);
    float r2 = r - __bfloat162float(b1);
    __nv_bfloat16 b2 = __float2bfloat16(r2);
    __nv_bfloat16* base = Y + (size_t)m * 6 * K + k;
    base[0 * K] = b0; base[1 * K] = b1; base[2 * K] = b0;
    base[3 * K] = b2; base[4 * K] = b1; base[5 * K] = b0;
}

// ================= warp-mma bf16 GEMM: C = A(MxK6) * W(NxK6)^T + b1 + b2 =====
// 128x128 tile, BK=32, 256 threads = 2x4 warps, warp tile 64x32.
#define PADH 40                    // smem row stride in halves (80B, conflict-free)
#define SBUF (128 * PADH)          // halves per buffer

__device__ __forceinline__ void ldsm4(uint32_t addr, uint32_t r[4]) {
    asm volatile("ldmatrix.sync.aligned.m8n8.x4.shared.b16 {%0,%1,%2,%3}, [%4];"
                 : "=r"(r[0]), "=r"(r[1]), "=r"(r[2]), "=r"(r[3]) : "r"(addr));
}
__device__ __forceinline__ void mma16816(float c[4], const uint32_t a[4],
                                         const uint32_t b[2]) {
    asm volatile(
        "mma.sync.aligned.m16n8k16.row.col.f32.bf16.bf16.f32 "
        "{%0,%1,%2,%3}, {%4,%5,%6,%7}, {%8,%9}, {%0,%1,%2,%3};"
        : "+f"(c[0]), "+f"(c[1]), "+f"(c[2]), "+f"(c[3])
        : "r"(a[0]), "r"(a[1]), "r"(a[2]), "r"(a[3]), "r"(b[0]), "r"(b[1]));
}

__global__ void __launch_bounds__(256)
gemm_mma(const __nv_bfloat16* __restrict__ A,   // [M][K6]
         const __nv_bfloat16* __restrict__ W,   // [NG][K6]
         const float* __restrict__ b1,
         const float* __restrict__ b2,
         float* __restrict__ C,                 // [M][NG]
         int K6) {
    __shared__ __align__(16) __nv_bfloat16 sA[2][SBUF];
    __shared__ __align__(16) __nv_bfloat16 sB[2][SBUF];

    const int tid = threadIdx.x;
    const int lane = tid & 31;
    const int wid = tid >> 5;
    const int warpm = wid >> 2;     // 0..1
    const int warpn = wid & 3;      // 0..3
    const int n0 = blockIdx.x * 128;
    const int m0 = blockIdx.y * 128;

    // gmem->smem load mapping: each thread moves 2 uint4 per matrix per ktile
    const int lr = tid >> 2;        // 0..63
    const int c4 = tid & 3;         // 16B chunk within 32-half row
    const size_t aoff0 = (size_t)(m0 + lr) * K6 + c4 * 8;
    const size_t aoff1 = aoff0 + (size_t)64 * K6;
    const size_t boff0 = (size_t)(n0 + lr) * K6 + c4 * 8;
    const size_t boff1 = boff0 + (size_t)64 * K6;
    const int sidx0 = lr * PADH + c4 * 8;
    const int sidx1 = (lr + 64) * PADH + c4 * 8;

    const uint32_t sAb = smem_u32(sA);
    const uint32_t sBb = smem_u32(sB);

    // ldmatrix per-lane address components
    const int rowoff = ((lane >> 3) & 1) * 8 + (lane & 7);
    const int koffA  = (lane >> 4) * 8;
    const int noff   = ((lane >> 4) << 3) + (lane & 7);
    const int koffB  = ((lane >> 3) & 1) * 8;

    float acc[4][4][4];
#pragma unroll
    for (int i = 0; i < 4; i++)
#pragma unroll
        for (int j = 0; j < 4; j++)
#pragma unroll
            for (int q = 0; q < 4; q++) acc[i][j][q] = 0.f;

    // preload ktile 0
    uint4 vA0 = *reinterpret_cast<const uint4*>(A + aoff0);
    uint4 vA1 = *reinterpret_cast<const uint4*>(A + aoff1);
    uint4 vB0 = *reinterpret_cast<const uint4*>(W + boff0);
    uint4 vB1 = *reinterpret_cast<const uint4*>(W + boff1);
    *reinterpret_cast<uint4*>(&sA[0][sidx0]) = vA0;
    *reinterpret_cast<uint4*>(&sA[0][sidx1]) = vA1;
    *reinterpret_cast<uint4*>(&sB[0][sidx0]) = vB0;
    *reinterpret_cast<uint4*>(&sB[0][sidx1]) = vB1;
    __syncthreads();

    const int nkt = K6 / 32;
    for (int kt = 0; kt < nkt; kt++) {
        const int cur = kt & 1;
        if (kt + 1 < nkt) {
            const size_t ko = (size_t)(kt + 1) * 32;
            vA0 = *reinterpret_cast<const uint4*>(A + aoff0 + ko);
            vA1 = *reinterpret_cast<const uint4*>(A + aoff1 + ko);
            vB0 = *reinterpret_cast<const uint4*>(W + boff0 + ko);
            vB1 = *reinterpret_cast<const uint4*>(W + boff1 + ko);
        }
        const uint32_t baseA = sAb + cur * (SBUF * 2);
        const uint32_t baseB = sBb + cur * (SBUF * 2);
#pragma unroll
        for (int ks = 0; ks < 2; ks++) {
            uint32_t af[4][4];
            uint32_t bf[4][2];
#pragma unroll
            for (int mf = 0; mf < 4; mf++) {
                int mrow = warpm * 64 + mf * 16 + rowoff;
                ldsm4(baseA + (uint32_t)(mrow * PADH + ks * 16 + koffA) * 2, af[mf]);
            }
#pragma unroll
            for (int p = 0; p < 2; p++) {
                uint32_t rr[4];
                int nrow = warpn * 32 + p * 16 + noff;
                ldsm4(baseB + (uint32_t)(nrow * PADH + ks * 16 + koffB) * 2, rr);
                bf[2 * p][0] = rr[0];     bf[2 * p][1] = rr[1];
                bf[2 * p + 1][0] = rr[2]; bf[2 * p + 1][1] = rr[3];
            }
#pragma unroll
            for (int mf = 0; mf < 4; mf++)
#pragma unroll
                for (int nf = 0; nf < 4; nf++)
                    mma16816(acc[mf][nf], af[mf], bf[nf]);
        }
        if (kt + 1 < nkt) {
            const int nb = (kt + 1) & 1;
            *reinterpret_cast<uint4*>(&sA[nb][sidx0]) = vA0;
            *reinterpret_cast<uint4*>(&sA[nb][sidx1]) = vA1;
            *reinterpret_cast<uint4*>(&sB[nb][sidx0]) = vB0;
            *reinterpret_cast<uint4*>(&sB[nb][sidx1]) = vB1;
        }
        __syncthreads();
    }

    // epilogue: fp32 + biases
#pragma unroll
    for (int nf = 0; nf < 4; nf++) {
        const int col = n0 + warpn * 32 + nf * 8 + (lane & 3) * 2;
        const float bx = b1[col] + b2[col];
        const float by = b1[col + 1] + b2[col + 1];
#pragma unroll
        for (int mf = 0; mf < 4; mf++) {
            const int row = m0 + warpm * 64 + mf * 16 + (lane >> 2);
            float2 v0 = make_float2(acc[mf][nf][0] + bx, acc[mf][nf][1] + by);
            float2 v1 = make_float2(acc[mf][nf][2] + bx, acc[mf][nf][3] + by);
            *reinterpret_cast<float2*>(C + (size_t)row * NG + col) = v0;
            *reinterpret_cast<float2*>(C + (size_t)(row + 8) * NG + col) = v1;
        }
    }
}

// ---------------- persistent bidirectional LSTM layer ------------------------
__global__ void __launch_bounds__(128)
lstm_layer(const float* __restrict__ G,
           const float* __restrict__ Whh,
           const float* __restrict__ h0,
           const float* __restrict__ c0,
           float* __restrict__ hbuf,
           float* __restrict__ Hcat) {
    const int dir = blockIdx.y;
    const int u0 = blockIdx.x * 8;
    const int tid = threadIdx.x;
    const float* W = Whh + (size_t)dir * 2048 * HD;

    __shared__ float Hs[16][68];
    __shared__ float Ws[16][36];
    __shared__ float gs[4][64][8];

    float cr[4];
#pragma unroll
    for (int i = 0; i < 4; i++) {
        int p = tid + i * 128;
        int b = p >> 3, ul = p & 7;
        size_t idx = (size_t)dir * BB * HD + b * HD + u0 + ul;
        cr[i] = c0[idx];
        hbuf[idx] = h0[idx];
    }
    grid_barrier(128);

    const int b0  = (tid >> 3) * 4;
    const int cg0 = (tid & 7) * 4;
    const int lcc = tid & 31;
    const int lgate = lcc >> 3;
    const int lu = u0 + (lcc & 7);
    const int lkq = tid >> 5;
    const int lb = tid & 63;
    const int hkq0 = tid >> 6;

    for (int s = 0; s < TT; s++) {
        const int t = dir ? (TT - 1 - s) : s;
        const float* h = hbuf + (size_t)(s & 1) * 2 * BB * HD
                              + (size_t)dir * BB * HD;
        float* ho = hbuf + (size_t)((s + 1) & 1) * 2 * BB * HD
                         + (size_t)dir * BB * HD;

        float acc[4][4];
#pragma unroll
        for (int i = 0; i < 4; i++)
#pragma unroll
            for (int j = 0; j < 4; j++) acc[i][j] = 0.f;

        for (int kt = 0; kt < HD; kt += 16) {
#pragma unroll
            for (int itq = 0; itq < 2; itq++) {
                int kq = hkq0 + itq * 2;
                float4 v = *reinterpret_cast<const float4*>(&h[lb * HD + kt + kq * 4]);
                Hs[kq * 4 + 0][lb] = v.x; Hs[kq * 4 + 1][lb] = v.y;
                Hs[kq * 4 + 2][lb] = v.z; Hs[kq * 4 + 3][lb] = v.w;
            }
            {
                float4 v = *reinterpret_cast<const float4*>(
                    &W[(size_t)(lgate * HD + lu) * HD + kt + lkq * 4]);
                Ws[lkq * 4 + 0][lcc] = v.x; Ws[lkq * 4 + 1][lcc] = v.y;
                Ws[lkq * 4 + 2][lcc] = v.z; Ws[lkq * 4 + 3][lcc] = v.w;
            }
            __syncthreads();
#pragma unroll
            for (int k = 0; k < 16; k++) {
                float4 hv = *reinterpret_cast<const float4*>(&Hs[k][b0]);
                float4 wv = *reinterpret_cast<const float4*>(&Ws[k][cg0]);
                float ar[4] = {hv.x, hv.y, hv.z, hv.w};
                float br[4] = {wv.x, wv.y, wv.z, wv.w};
#pragma unroll
                for (int i = 0; i < 4; i++)
#pragma unroll
                    for (int j = 0; j < 4; j++) acc[i][j] += ar[i] * br[j];
            }
            __syncthreads();
        }

        const int row0 = t * BB;
#pragma unroll
        for (int i = 0; i < 4; i++) {
            int b = b0 + i;
#pragma unroll
            for (int j = 0; j < 4; j++) {
                int cc = cg0 + j;
                int gate = cc >> 3;
                int ul = cc & 7;
                float v = acc[i][j] +
                    G[(size_t)(row0 + b) * NG + dir * 2048 + gate * HD + u0 + ul];
                gs[gate][b][ul] = v;
            }
        }
        __syncthreads();

#pragma unroll
        for (int i = 0; i < 4; i++) {
            int p = tid + i * 128;
            int b = p >> 3;
            int ul = p & 7;
            int u = u0 + ul;
            float ig = gs[0][b][ul];
            float fg = gs[1][b][ul];
            float gg = gs[2][b][ul];
            float og = gs[3][b][ul];
            float si = 1.f / (1.f + expf(-ig));
            float sf = 1.f / (1.f + expf(-fg));
            float so = 1.f / (1.f + expf(-og));
            float cn = sf * cr[i] + si * tanhf(gg);
            float hn = so * tanhf(cn);
            cr[i] = cn;
            ho[b * HD + u] = hn;
            Hcat[(size_t)t * BB * HH + b * HH + dir * HD + u] = hn;
        }
        grid_barrier(128);
    }
}

// ---------------- final linear ------------------------------------------------
__global__ void linear_feats(const float* __restrict__ H1,
                             const float* __restrict__ lw,
                             const float* __restrict__ lb,
                             float* __restrict__ feats) {
    int warp = (blockIdx.x * blockDim.x + threadIdx.x) >> 5;
    int lane = threadIdx.x & 31;
    if (warp >= MROWS) return;
    const float* hrow = H1 + (size_t)warp * HH;
    float acc[CC];
#pragma unroll
    for (int c = 0; c < CC; c++) acc[c] = 0.f;
    for (int k = lane; k < HH; k += 32) {
        float hv = hrow[k];
#pragma unroll
        for (int c = 0; c < CC; c++) acc[c] += hv * lw[c * HH + k];
    }
#pragma unroll
    for (int c = 0; c < CC; c++) {
        float v = acc[c];
#pragma unroll
        for (int o = 16; o; o >>= 1) v += __shfl_down_sync(0xffffffffu, v, o);
        if (lane == 0) {
            int t = warp >> 6, b = warp & 63;
            feats[((size_t)b * TT + t) * CC + c] = v + lb[c];
        }
    }
}

// ---------------- Viterbi decode ----------------------------------------------
__global__ void viterbi_kernel(const float* __restrict__ feats,
                               const float* __restrict__ trans,
                               float* __restrict__ out,
                               int write_scores, int write_paths, int path_off) {
    const int b = blockIdx.x;
    const int c = threadIdx.x;
    __shared__ unsigned char bp[TT][CC];

    float tr[CC];
#pragma unroll
    for (int p = 0; p < CC; p++) tr[p] = trans[c * CC + p];

    float fv = (c == START_TAG) ? 0.f : -10000.f;
    const float* f = feats + (size_t)b * TT * CC;

    for (int t = 0; t < TT; t++) {
        float best = -3.4e38f;
        int arg = 0;
#pragma unroll
        for (int p = 0; p < CC; p++) {
            float sc = __shfl_sync(0x0000ffffu, fv, p) + tr[p];
            if (sc > best) { best = sc; arg = p; }
        }
        bp[t][c] = (unsigned char)arg;
        fv = best + f[t * CC + c];
    }

    float term = fv + trans[STOP_TAG * CC + c];
    float bv = term;
    int bi = c;
#pragma unroll
    for (int o = 8; o; o >>= 1) {
        float ov = __shfl_down_sync(0x0000ffffu, bv, o);
        int oi = __shfl_down_sync(0x0000ffffu, bi, o);
        if (ov > bv || (ov == bv && oi < bi)) { bv = ov; bi = oi; }
    }
    bv = __shfl_sync(0x0000ffffu, bv, 0);
    bi = __shfl_sync(0x0000ffffu, bi, 0);

    if (c == 0) {
        if (write_scores) out[b] = bv;
        if (write_paths) {
            int tag = bi;
            for (int t = TT - 1; t >= 0; t--) {
                out[path_off + b * TT + t] = (float)tag;
                tag = bp[t][tag];
            }
        }
    }
}

// ---------------- launch ------------------------------------------------------
extern "C" void kernel_launch(void* const* d_in, const int* in_sizes, int n_in,
                              void* d_out, int out_size) {
    const int*   sent    = (const int*)  d_in[0];
    const float* emb     = (const float*)d_in[1];
    const float* wih0    = (const float*)d_in[2];
    const float* whh0    = (const float*)d_in[3];
    const float* bih0    = (const float*)d_in[4];
    const float* bhh0    = (const float*)d_in[5];
    const float* wih1    = (const float*)d_in[6];
    const float* whh1    = (const float*)d_in[7];
    const float* bih1    = (const float*)d_in[8];
    const float* bhh1    = (const float*)d_in[9];
    const float* linw    = (const float*)d_in[10];
    const float* linb    = (const float*)d_in[11];
    const float* trans   = (const float*)d_in[12];
    const float* h0      = (const float*)d_in[13];
    const float* c0      = (const float*)d_in[14];

    float *pX0, *pG, *pH0, *pH1, *pfe, *phb;
    __nv_bfloat16 *pAs, *pWs;
    cudaGetSymbolAddress((void**)&pX0, g_X0);
    cudaGetSymbolAddress((void**)&pG,  g_G);
    cudaGetSymbolAddress((void**)&pH0, g_H0);
    cudaGetSymbolAddress((void**)&pH1, g_H1);
    cudaGetSymbolAddress((void**)&pfe, g_feats);
    cudaGetSymbolAddress((void**)&phb, g_hbuf);
    cudaGetSymbolAddress((void**)&pAs, g_As);
    cudaGetSymbolAddress((void**)&pWs, g_Ws);

    // 1) embedding gather
    embed_kernel<<<MROWS, 128>>>(sent, emb, pX0);

    // 2) layer-0: split + tensor GEMM (K6 = 6*512 = 3072)
    {
        long long tA = (long long)MROWS * EE;
        long long tW = (long long)NG * EE;
        splitA_kernel<<<(unsigned)((tA + 255) / 256), 256>>>(pX0, pAs, EE, tA);
        splitW_kernel<<<(unsigned)((tW + 255) / 256), 256>>>(wih0, pWs, EE, tW);
        gemm_mma<<<dim3(NG / 128, MROWS / 128), 256>>>(
            pAs, pWs, bih0, bhh0, pG, 6 * EE);
    }

    // 3) layer-0 recurrence
    lstm_layer<<<dim3(64, 2), 128>>>(pG, whh0, h0, c0, phb, pH0);

    // 4) layer-1: split + tensor GEMM (K6 = 6*1024 = 6144)
    {
        long long tA = (long long)MROWS * HH;
        long long tW = (long long)NG * HH;
        splitA_kernel<<<(unsigned)((tA + 255) / 256), 256>>>(pH0, pAs, HH, tA);
        splitW_kernel<<<(unsigned)((tW + 255) / 256), 256>>>(wih1, pWs, HH, tW);
        gemm_mma<<<dim3(NG / 128, MROWS / 128), 256>>>(
            pAs, pWs, bih1, bhh1, pG, 6 * HH);
    }

    // 5) layer-1 recurrence
    lstm_layer<<<dim3(64, 2), 128>>>(pG, whh1,
                                     h0 + 2 * BB * HD, c0 + 2 * BB * HD,
                                     phb, pH1);

    // 6) linear -> feats
    linear_feats<<<(MROWS * 32 + 255) / 256, 256>>>(pH1, linw, linb, pfe);

    // 7) Viterbi decode + output write
    float* out = (float*)d_out;
    int write_scores, write_paths, path_off;
    if (out_size >= BB + BB * TT) { write_scores = 1; write_paths = 1; path_off = BB; }
    else if (out_size == BB * TT) { write_scores = 0; write_paths = 1; path_off = 0; }
    else                          { write_scores = 1; write_paths = 0; path_off = 0; }
    viterbi_kernel<<<BB, CC>>>(pfe, trans, out, write_scores, write_paths, path_off);
}

// round 6
// speedup vs baseline: 1.3286x; 1.3286x over previous
#include <cuda_runtime.h>
#include <cuda_bf16.h>
#include <math.h>
#include <stdint.h>

// Problem dims
#define TT 512
#define BB 64
#define EE 512
#define HD 512
#define HH 1024
#define CC 16
#define START_TAG 14
#define STOP_TAG 15
#define NG 4096          // 2 dirs * 4 gates * HD
#define MROWS (TT*BB)    // 32768

// ---------------- scratch ------------------------------------------------------
__device__ float g_X0[(size_t)MROWS * EE];
__device__ float g_G [(size_t)MROWS * NG];
__device__ float g_H0[(size_t)MROWS * HH];
__device__ float g_H1[(size_t)MROWS * HH];
__device__ __nv_bfloat16 g_As[(size_t)MROWS * 6 * HH];
__device__ __nv_bfloat16 g_Ws[(size_t)NG * 6 * HH];
__device__ float g_feats[(size_t)BB * TT * CC];
__device__ float g_hbuf[2 * 2 * BB * HD];

__device__ unsigned int g_bar_count;
__device__ unsigned int g_bar_gen;

__device__ __forceinline__ void grid_barrier(int nblk) {
    __syncthreads();
    if (threadIdx.x == 0) {
        __threadfence();
        unsigned int gen = *(volatile unsigned int*)&g_bar_gen;
        if (atomicAdd(&g_bar_count, 1u) == (unsigned)(nblk - 1)) {
            g_bar_count = 0;
            __threadfence();
            atomicAdd(&g_bar_gen, 1u);
        } else {
            unsigned int cur;
            do {
                asm volatile("ld.acquire.gpu.u32 %0, [%1];"
                             : "=r"(cur) : "l"(&g_bar_gen));
            } while (cur == gen);
        }
    }
    __syncthreads();
}

__device__ __forceinline__ uint32_t smem_u32(const void* p) {
    uint32_t a;
    asm("{ .reg .u64 t; cvta.to.shared.u64 t, %1; cvt.u32.u64 %0, t; }"
        : "=r"(a) : "l"(p));
    return a;
}

// ---------------- embedding gather ---------------------------------------------
__global__ void embed_kernel(const int* __restrict__ sent,
                             const float* __restrict__ emb,
                             float* __restrict__ X0) {
    int m = blockIdx.x;
    int t = m >> 6;
    int b = m & 63;
    int tok = sent[b * TT + t];
    const float4* src = reinterpret_cast<const float4*>(emb + (size_t)tok * EE);
    float4* dst = reinterpret_cast<float4*>(X0 + (size_t)m * EE);
    dst[threadIdx.x] = src[threadIdx.x];
}

// ---------------- fp32 -> 3-term bf16 split (K-concatenated, exact) ------------
__global__ void splitA_kernel(const float* __restrict__ X,
                              __nv_bfloat16* __restrict__ Y,
                              int K, long long total) {
    long long idx = (long long)blockIdx.x * blockDim.x + threadIdx.x;
    if (idx >= total) return;
    int m = (int)(idx / K);
    int k = (int)(idx % K);
    float a = X[idx];
    __nv_bfloat16 b0 = __float2bfloat16(a);
    float r = a - __bfloat162float(b0);
    __nv_bfloat16 b1 = __float2bfloat16(r);
    float r2 = r - __bfloat162float(b1);
    __nv_bfloat16 b2 = __float2bfloat16(r2);
    __nv_bfloat16* base = Y + (size_t)m * 6 * K + k;
    base[0 * K] = b0; base[1 * K] = b0; base[2 * K] = b1;
    base[3 * K] = b0; base[4 * K] = b1; base[5 * K] = b2;
}
__global__ void splitW_kernel(const float* __restrict__ X,
                              __nv_bfloat16* __restrict__ Y,
                              int K, long long total) {
    long long idx = (long long)blockIdx.x * blockDim.x + threadIdx.x;
    if (idx >= total) return;
    int m = (int)(idx / K);
    int k = (int)(idx % K);
    float a = X[idx];
    __nv_bfloat16 b0 = __float2bfloat16(a);
    float r = a - __bfloat162float(b0);
    __nv_bfloat16 b1 = __float2bfloat16(r);
    float r2 = r - __bfloat162float(b1);
    __nv_bfloat16 b2 = __float2bfloat16(r2);
    __nv_bfloat16* base = Y + (size_t)m * 6 * K + k;
    base[0 * K] = b0; base[1 * K] = b1; base[2 * K] = b0;
    base[3 * K] = b2; base[4 * K] = b1; base[5 * K] = b0;
}

// ================= pipelined warp-mma bf16 GEMM ==================================
// C[M][NG] = A(MxK6) * W(NGxK6)^T + b1 + b2.  128x256 tile, BK=32, 3-stage cp.async,
// 8 warps, 64x64 warp tiles.
#define BM 128
#define BN 256
#define BK 32
#define NSTAGE 3
#define PADH 40
#define SA_BYTES (BM * PADH * 2)
#define SB_BYTES (BN * PADH * 2)
#define GEMM_SMEM (NSTAGE * (SA_BYTES + SB_BYTES))   // 92160

__device__ __forceinline__ void ldsm4(uint32_t addr, uint32_t r[4]) {
    asm volatile("ldmatrix.sync.aligned.m8n8.x4.shared.b16 {%0,%1,%2,%3}, [%4];"
                 : "=r"(r[0]), "=r"(r[1]), "=r"(r[2]), "=r"(r[3]) : "r"(addr));
}
__device__ __forceinline__ void mma16816(float c[4], const uint32_t a[4],
                                         const uint32_t b[2]) {
    asm volatile(
        "mma.sync.aligned.m16n8k16.row.col.f32.bf16.bf16.f32 "
        "{%0,%1,%2,%3}, {%4,%5,%6,%7}, {%8,%9}, {%0,%1,%2,%3};"
        : "+f"(c[0]), "+f"(c[1]), "+f"(c[2]), "+f"(c[3])
        : "r"(a[0]), "r"(a[1]), "r"(a[2]), "r"(a[3]), "r"(b[0]), "r"(b[1]));
}
__device__ __forceinline__ void cp16(uint32_t dst, const void* src) {
    asm volatile("cp.async.cg.shared.global [%0], [%1], 16;" :: "r"(dst), "l"(src));
}
__device__ __forceinline__ void cp_commit() {
    asm volatile("cp.async.commit_group;");
}
template <int N>
__device__ __forceinline__ void cp_wait() {
    asm volatile("cp.async.wait_group %0;" :: "n"(N));
}

__global__ void __launch_bounds__(256)
gemm_mma(const __nv_bfloat16* __restrict__ A,
         const __nv_bfloat16* __restrict__ W,
         const float* __restrict__ b1,
         const float* __restrict__ b2,
         float* __restrict__ C,
         int K6) {
    extern __shared__ char dsm[];
    const uint32_t sAb = smem_u32(dsm);
    const uint32_t sBb = sAb + NSTAGE * SA_BYTES;

    const int tid = threadIdx.x;
    const int lane = tid & 31;
    const int wid = tid >> 5;
    const int warpm = wid >> 2;     // 0..1
    const int warpn = wid & 3;      // 0..3
    const int n0 = blockIdx.x * BN;
    const int m0 = blockIdx.y * BM;

    const int rowoff = ((lane >> 3) & 1) * 8 + (lane & 7);
    const int koffA  = (lane >> 4) * 8;
    const int noff   = ((lane >> 4) << 3) + (lane & 7);
    const int koffB  = ((lane >> 3) & 1) * 8;

    float acc[4][8][4];
#pragma unroll
    for (int i = 0; i < 4; i++)
#pragma unroll
        for (int j = 0; j < 8; j++)
#pragma unroll
            for (int q = 0; q < 4; q++) acc[i][j][q] = 0.f;

    auto issue = [&](int stage, int kt) {
        const int kb = kt * BK;
        const uint32_t sa = sAb + stage * SA_BYTES;
        const uint32_t sb = sBb + stage * SB_BYTES;
#pragma unroll
        for (int q = 0; q < 2; q++) {
            int id = tid + q * 256;
            int r = id >> 2, c4 = id & 3;
            cp16(sa + (uint32_t)(r * PADH + c4 * 8) * 2,
                 A + (size_t)(m0 + r) * K6 + kb + c4 * 8);
        }
#pragma unroll
        for (int q = 0; q < 4; q++) {
            int id = tid + q * 256;
            int r = id >> 2, c4 = id & 3;
            cp16(sb + (uint32_t)(r * PADH + c4 * 8) * 2,
                 W + (size_t)(n0 + r) * K6 + kb + c4 * 8);
        }
    };

    issue(0, 0); cp_commit();
    issue(1, 1); cp_commit();

    const int nkt = K6 / BK;
    int stage = 0;
    for (int kt = 0; kt < nkt; kt++) {
        cp_wait<1>();
        __syncthreads();
        if (kt + 2 < nkt) {
            int ns = stage + 2; if (ns >= NSTAGE) ns -= NSTAGE;
            issue(ns, kt + 2);
        }
        cp_commit();

        const uint32_t sa = sAb + stage * SA_BYTES;
        const uint32_t sb = sBb + stage * SB_BYTES;
#pragma unroll
        for (int ks = 0; ks < 2; ks++) {
            uint32_t af[4][4];
            uint32_t bf[8][2];
#pragma unroll
            for (int mf = 0; mf < 4; mf++) {
                int mrow = warpm * 64 + mf * 16 + rowoff;
                ldsm4(sa + (uint32_t)(mrow * PADH + ks * 16 + koffA) * 2, af[mf]);
            }
#pragma unroll
            for (int p = 0; p < 4; p++) {
                uint32_t rr[4];
                int nrow = warpn * 64 + p * 16 + noff;
                ldsm4(sb + (uint32_t)(nrow * PADH + ks * 16 + koffB) * 2, rr);
                bf[2 * p][0] = rr[0];     bf[2 * p][1] = rr[1];
                bf[2 * p + 1][0] = rr[2]; bf[2 * p + 1][1] = rr[3];
            }
#pragma unroll
            for (int mf = 0; mf < 4; mf++)
#pragma unroll
                for (int nf = 0; nf < 8; nf++)
                    mma16816(acc[mf][nf], af[mf], bf[nf]);
        }
        if (++stage == NSTAGE) stage = 0;
    }

    // epilogue: fp32 + biases
#pragma unroll
    for (int nf = 0; nf < 8; nf++) {
        const int col = n0 + warpn * 64 + nf * 8 + (lane & 3) * 2;
        const float bx = b1[col] + b2[col];
        const float by = b1[col + 1] + b2[col + 1];
#pragma unroll
        for (int mf = 0; mf < 4; mf++) {
            const int row = m0 + warpm * 64 + mf * 16 + (lane >> 2);
            float2 v0 = make_float2(acc[mf][nf][0] + bx, acc[mf][nf][1] + by);
            float2 v1 = make_float2(acc[mf][nf][2] + bx, acc[mf][nf][3] + by);
            *reinterpret_cast<float2*>(C + (size_t)row * NG + col) = v0;
            *reinterpret_cast<float2*>(C + (size_t)(row + 8) * NG + col) = v1;
        }
    }
}

// ---------------- persistent bidirectional LSTM layer ---------------------------
// W slice persistent in smem; h chunks double-buffered (1 sync per ktile).
#define LS_WS 0                         // float Ws[512][32]   = 65536 B
#define LS_HS 65536                     // float Hs[2][16][68] = 8704 B
#define LS_GS (65536 + 8704)            // float gs[4][64][8]  = 8192 B
#define LSTM_SMEM (LS_GS + 8192)        // 82432 B

__global__ void __launch_bounds__(128)
lstm_layer(const float* __restrict__ G,
           const float* __restrict__ Whh,
           const float* __restrict__ h0,
           const float* __restrict__ c0,
           float* __restrict__ hbuf,
           float* __restrict__ Hcat) {
    extern __shared__ char dsm[];
    float (*Ws)[32]     = reinterpret_cast<float(*)[32]>(dsm + LS_WS);
    float (*Hs)[16][68] = reinterpret_cast<float(*)[16][68]>(dsm + LS_HS);
    float (*gs)[64][8]  = reinterpret_cast<float(*)[64][8]>(dsm + LS_GS);

    const int dir = blockIdx.y;
    const int u0 = blockIdx.x * 8;
    const int tid = threadIdx.x;
    const float* W = Whh + (size_t)dir * 2048 * HD;

    const int lcc = tid & 31;
    const int lgate = lcc >> 3;
    const int lu = u0 + (lcc & 7);
    const int lkq = tid >> 5;
    const int lb = tid & 63;
    const int hkq0 = tid >> 6;

    // persistent W load (conflict-free transpose, once)
    for (int kt = 0; kt < HD; kt += 16) {
        float4 v = *reinterpret_cast<const float4*>(
            &W[(size_t)(lgate * HD + lu) * HD + kt + lkq * 4]);
        Ws[kt + lkq * 4 + 0][lcc] = v.x; Ws[kt + lkq * 4 + 1][lcc] = v.y;
        Ws[kt + lkq * 4 + 2][lcc] = v.z; Ws[kt + lkq * 4 + 3][lcc] = v.w;
    }

    float cr[4];
#pragma unroll
    for (int i = 0; i < 4; i++) {
        int p = tid + i * 128;
        int b = p >> 3, ul = p & 7;
        size_t idx = (size_t)dir * BB * HD + b * HD + u0 + ul;
        cr[i] = c0[idx];
        hbuf[idx] = h0[idx];
    }
    grid_barrier(128);      // covers Ws (contains __syncthreads) + h init

    const int b0  = (tid >> 3) * 4;
    const int cg0 = (tid & 7) * 4;
    const int g0  = cg0 >> 3;           // gate of this 4-col group
    const int ul0 = cg0 & 7;

    for (int s = 0; s < TT; s++) {
        const int t = dir ? (TT - 1 - s) : s;
        const float* h = hbuf + (size_t)(s & 1) * 2 * BB * HD
                              + (size_t)dir * BB * HD;
        float* ho = hbuf + (size_t)((s + 1) & 1) * 2 * BB * HD
                         + (size_t)dir * BB * HD;

        // preload chunk 0
#pragma unroll
        for (int itq = 0; itq < 2; itq++) {
            int kq = hkq0 + itq * 2;
            float4 v = *reinterpret_cast<const float4*>(&h[lb * HD + kq * 4]);
            Hs[0][kq * 4 + 0][lb] = v.x; Hs[0][kq * 4 + 1][lb] = v.y;
            Hs[0][kq * 4 + 2][lb] = v.z; Hs[0][kq * 4 + 3][lb] = v.w;
        }
        __syncthreads();

        float acc[4][4];
#pragma unroll
        for (int i = 0; i < 4; i++)
#pragma unroll
            for (int j = 0; j < 4; j++) acc[i][j] = 0.f;

        for (int kt16 = 0; kt16 < 32; kt16++) {
            const int cur = kt16 & 1;
            float4 pv0, pv1;
            const bool pf = (kt16 < 31);
            if (pf) {
                const int kb = (kt16 + 1) * 16;
                pv0 = *reinterpret_cast<const float4*>(&h[lb * HD + kb + hkq0 * 4]);
                pv1 = *reinterpret_cast<const float4*>(&h[lb * HD + kb + (hkq0 + 2) * 4]);
            }
#pragma unroll
            for (int k = 0; k < 16; k++) {
                float4 hv = *reinterpret_cast<const float4*>(&Hs[cur][k][b0]);
                float4 wv = *reinterpret_cast<const float4*>(&Ws[kt16 * 16 + k][cg0]);
                float ar[4] = {hv.x, hv.y, hv.z, hv.w};
                float br[4] = {wv.x, wv.y, wv.z, wv.w};
#pragma unroll
                for (int i = 0; i < 4; i++)
#pragma unroll
                    for (int j = 0; j < 4; j++) acc[i][j] += ar[i] * br[j];
            }
            if (pf) {
                const int nb = cur ^ 1;
                Hs[nb][hkq0 * 4 + 0][lb] = pv0.x; Hs[nb][hkq0 * 4 + 1][lb] = pv0.y;
                Hs[nb][hkq0 * 4 + 2][lb] = pv0.z; Hs[nb][hkq0 * 4 + 3][lb] = pv0.w;
                Hs[nb][(hkq0 + 2) * 4 + 0][lb] = pv1.x;
                Hs[nb][(hkq0 + 2) * 4 + 1][lb] = pv1.y;
                Hs[nb][(hkq0 + 2) * 4 + 2][lb] = pv1.z;
                Hs[nb][(hkq0 + 2) * 4 + 3][lb] = pv1.w;
            }
            __syncthreads();
        }

        // add precomputed input gates (vectorized) and stage by gate
        const int row0 = t * BB;
#pragma unroll
        for (int i = 0; i < 4; i++) {
            int b = b0 + i;
            float4 gv = *reinterpret_cast<const float4*>(
                &G[(size_t)(row0 + b) * NG + dir * 2048 + g0 * HD + u0 + ul0]);
            gs[g0][b][ul0 + 0] = acc[i][0] + gv.x;
            gs[g0][b][ul0 + 1] = acc[i][1] + gv.y;
            gs[g0][b][ul0 + 2] = acc[i][2] + gv.z;
            gs[g0][b][ul0 + 3] = acc[i][3] + gv.w;
        }
        __syncthreads();

#pragma unroll
        for (int i = 0; i < 4; i++) {
            int p = tid + i * 128;
            int b = p >> 3;
            int ul = p & 7;
            int u = u0 + ul;
            float ig = gs[0][b][ul];
            float fg = gs[1][b][ul];
            float gg = gs[2][b][ul];
            float og = gs[3][b][ul];
            float si = 1.f / (1.f + expf(-ig));
            float sf = 1.f / (1.f + expf(-fg));
            float so = 1.f / (1.f + expf(-og));
            float cn = sf * cr[i] + si * tanhf(gg);
            float hn = so * tanhf(cn);
            cr[i] = cn;
            ho[b * HD + u] = hn;
            Hcat[(size_t)t * BB * HH + b * HH + dir * HD + u] = hn;
        }
        grid_barrier(128);
    }
}

// ---------------- final linear ---------------------------------------------------
__global__ void linear_feats(const float* __restrict__ H1,
                             const float* __restrict__ lw,
                             const float* __restrict__ lb,
                             float* __restrict__ feats) {
    int warp = (blockIdx.x * blockDim.x + threadIdx.x) >> 5;
    int lane = threadIdx.x & 31;
    if (warp >= MROWS) return;
    const float* hrow = H1 + (size_t)warp * HH;
    float acc[CC];
#pragma unroll
    for (int c = 0; c < CC; c++) acc[c] = 0.f;
    for (int k = lane; k < HH; k += 32) {
        float hv = hrow[k];
#pragma unroll
        for (int c = 0; c < CC; c++) acc[c] += hv * lw[c * HH + k];
    }
#pragma unroll
    for (int c = 0; c < CC; c++) {
        float v = acc[c];
#pragma unroll
        for (int o = 16; o; o >>= 1) v += __shfl_down_sync(0xffffffffu, v, o);
        if (lane == 0) {
            int t = warp >> 6, b = warp & 63;
            feats[((size_t)b * TT + t) * CC + c] = v + lb[c];
        }
    }
}

// ---------------- Viterbi decode --------------------------------------------------
__global__ void viterbi_kernel(const float* __restrict__ feats,
                               const float* __restrict__ trans,
                               float* __restrict__ out,
                               int write_scores, int write_paths, int path_off) {
    const int b = blockIdx.x;
    const int c = threadIdx.x;
    __shared__ unsigned char bp[TT][CC];

    float tr[CC];
#pragma unroll
    for (int p = 0; p < CC; p++) tr[p] = trans[c * CC + p];

    float fv = (c == START_TAG) ? 0.f : -10000.f;
    const float* f = feats + (size_t)b * TT * CC;

    for (int t = 0; t < TT; t++) {
        float best = -3.4e38f;
        int arg = 0;
#pragma unroll
        for (int p = 0; p < CC; p++) {
            float sc = __shfl_sync(0x0000ffffu, fv, p) + tr[p];
            if (sc > best) { best = sc; arg = p; }
        }
        bp[t][c] = (unsigned char)arg;
        fv = best + f[t * CC + c];
    }

    float term = fv + trans[STOP_TAG * CC + c];
    float bv = term;
    int bi = c;
#pragma unroll
    for (int o = 8; o; o >>= 1) {
        float ov = __shfl_down_sync(0x0000ffffu, bv, o);
        int oi = __shfl_down_sync(0x0000ffffu, bi, o);
        if (ov > bv || (ov == bv && oi < bi)) { bv = ov; bi = oi; }
    }
    bv = __shfl_sync(0x0000ffffu, bv, 0);
    bi = __shfl_sync(0x0000ffffu, bi, 0);

    if (c == 0) {
        if (write_scores) out[b] = bv;
        if (write_paths) {
            int tag = bi;
            for (int t = TT - 1; t >= 0; t--) {
                out[path_off + b * TT + t] = (float)tag;
                tag = bp[t][tag];
            }
        }
    }
}

// ---------------- launch -----------------------------------------------------------
extern "C" void kernel_launch(void* const* d_in, const int* in_sizes, int n_in,
                              void* d_out, int out_size) {
    const int*   sent    = (const int*)  d_in[0];
    const float* emb     = (const float*)d_in[1];
    const float* wih0    = (const float*)d_in[2];
    const float* whh0    = (const float*)d_in[3];
    const float* bih0    = (const float*)d_in[4];
    const float* bhh0    = (const float*)d_in[5];
    const float* wih1    = (const float*)d_in[6];
    const float* whh1    = (const float*)d_in[7];
    const float* bih1    = (const float*)d_in[8];
    const float* bhh1    = (const float*)d_in[9];
    const float* linw    = (const float*)d_in[10];
    const float* linb    = (const float*)d_in[11];
    const float* trans   = (const float*)d_in[12];
    const float* h0      = (const float*)d_in[13];
    const float* c0      = (const float*)d_in[14];

    float *pX0, *pG, *pH0, *pH1, *pfe, *phb;
    __nv_bfloat16 *pAs, *pWs;
    cudaGetSymbolAddress((void**)&pX0, g_X0);
    cudaGetSymbolAddress((void**)&pG,  g_G);
    cudaGetSymbolAddress((void**)&pH0, g_H0);
    cudaGetSymbolAddress((void**)&pH1, g_H1);
    cudaGetSymbolAddress((void**)&pfe, g_feats);
    cudaGetSymbolAddress((void**)&phb, g_hbuf);
    cudaGetSymbolAddress((void**)&pAs, g_As);
    cudaGetSymbolAddress((void**)&pWs, g_Ws);

    cudaFuncSetAttribute(gemm_mma, cudaFuncAttributeMaxDynamicSharedMemorySize,
                         GEMM_SMEM);
    cudaFuncSetAttribute(lstm_layer, cudaFuncAttributeMaxDynamicSharedMemorySize,
                         LSTM_SMEM);

    // 1) embedding gather
    embed_kernel<<<MROWS, 128>>>(sent, emb, pX0);

    // 2) layer-0: split + pipelined tensor GEMM (K6 = 3072)
    {
        long long tA = (long long)MROWS * EE;
        long long tW = (long long)NG * EE;
        splitA_kernel<<<(unsigned)((tA + 255) / 256), 256>>>(pX0, pAs, EE, tA);
        splitW_kernel<<<(unsigned)((tW + 255) / 256), 256>>>(wih0, pWs, EE, tW);
        gemm_mma<<<dim3(NG / BN, MROWS / BM), 256, GEMM_SMEM>>>(
            pAs, pWs, bih0, bhh0, pG, 6 * EE);
    }

    // 3) layer-0 recurrence
    lstm_layer<<<dim3(64, 2), 128, LSTM_SMEM>>>(pG, whh0, h0, c0, phb, pH0);

    // 4) layer-1: split + pipelined tensor GEMM (K6 = 6144)
    {
        long long tA = (long long)MROWS * HH;
        long long tW = (long long)NG * HH;
        splitA_kernel<<<(unsigned)((tA + 255) / 256), 256>>>(pH0, pAs, HH, tA);
        splitW_kernel<<<(unsigned)((tW + 255) / 256), 256>>>(wih1, pWs, HH, tW);
        gemm_mma<<<dim3(NG / BN, MROWS / BM), 256, GEMM_SMEM>>>(
            pAs, pWs, bih1, bhh1, pG, 6 * HH);
    }

    // 5) layer-1 recurrence
    lstm_layer<<<dim3(64, 2), 128, LSTM_SMEM>>>(pG, whh1,
                                                h0 + 2 * BB * HD, c0 + 2 * BB * HD,
                                                phb, pH1);

    // 6) linear -> feats
    linear_feats<<<(MROWS * 32 + 255) / 256, 256>>>(pH1, linw, linb, pfe);

    // 7) Viterbi decode + output write
    float* out = (float*)d_out;
    int write_scores, write_paths, path_off;
    if (out_size >= BB + BB * TT) { write_scores = 1; write_paths = 1; path_off = BB; }
    else if (out_size == BB * TT) { write_scores = 0; write_paths = 1; path_off = 0; }
    else                          { write_scores = 1; write_paths = 0; path_off = 0; }
    viterbi_kernel<<<BB, CC>>>(pfe, trans, out, write_scores, write_paths, path_off);
}